// round 7
// baseline (speedup 1.0000x reference)
#include <cuda_runtime.h>
#include <cuda_fp16.h>
#include <cstdint>

// Problem dims (fixed)
#define BDIM 256
#define TDIM 500
#define IDIM 1024
#define ODIM 2048
#define M_GEMM (BDIM * TDIM)   // 128000
#define N_GEMM ODIM            // 2048
#define K_GEMM IDIM            // 1024

// GEMM tiling: 256x128 CTA, 512 threads, 16 warps in 8(m) x 2(n), 32x64 per warp
#define BM 256
#define BN 128
#define BK 32
#define STAGES 5
#define NCHUNK (K_GEMM / BK)   // 32

// Padded smem strides (bytes): 16B-chunk counts coprime with 8 -> conflict-free ldmatrix
#define A_STRIDE 80            // 32 halves (64B) + 16B pad   (5 chunks)
#define B_STRIDE 272           // 128 halves (256B) + 16B pad (17 chunks)
#define A_STAGE_BYTES (256 * A_STRIDE)   // 20480
#define B_STAGE_BYTES (32 * B_STRIDE)    // 8704
#define STAGE_BYTES (A_STAGE_BYTES + B_STAGE_BYTES)  // 29184
#define SMEM_TOTAL (STAGES * STAGE_BYTES)            // 145920 (1 CTA/SM)

// Device scratch (no runtime allocation allowed)
__device__ __align__(1024) __half g_h [(size_t)M_GEMM * N_GEMM];  // 512 MB (h in fp16)
__device__ __align__(1024) __half g_xh[(size_t)M_GEMM * K_GEMM];  // 256 MB
__device__ __align__(1024) __half g_wh[(size_t)K_GEMM * N_GEMM];  // 4 MB

// ---------------------------------------------------------------------------
__device__ __forceinline__ uint32_t smem_u32(const void* p) {
    uint32_t a;
    asm("{ .reg .u64 t; cvta.to.shared.u64 t, %1; cvt.u32.u64 %0, t; }" : "=r"(a) : "l"(p));
    return a;
}
__device__ __forceinline__ void cp16(uint32_t dst, const void* src) {
    asm volatile("cp.async.cg.shared.global [%0], [%1], 16;" :: "r"(dst), "l"(src));
}
#define CP_COMMIT() asm volatile("cp.async.commit_group;" ::: "memory")

__device__ __forceinline__ void ldsm_x4(uint32_t* r, uint32_t addr) {
    asm volatile("ldmatrix.sync.aligned.m8n8.x4.shared.b16 {%0,%1,%2,%3}, [%4];"
                 : "=r"(r[0]), "=r"(r[1]), "=r"(r[2]), "=r"(r[3]) : "r"(addr));
}
__device__ __forceinline__ void ldsm_x4_t(uint32_t* r, uint32_t addr) {
    asm volatile("ldmatrix.sync.aligned.m8n8.x4.trans.shared.b16 {%0,%1,%2,%3}, [%4];"
                 : "=r"(r[0]), "=r"(r[1]), "=r"(r[2]), "=r"(r[3]) : "r"(addr));
}
__device__ __forceinline__ void mma16816(float* c, const uint32_t* a, uint32_t b0, uint32_t b1) {
    asm volatile(
        "mma.sync.aligned.m16n8k16.row.col.f32.f16.f16.f32 "
        "{%0,%1,%2,%3}, {%4,%5,%6,%7}, {%8,%9}, {%0,%1,%2,%3};"
        : "+f"(c[0]), "+f"(c[1]), "+f"(c[2]), "+f"(c[3])
        : "r"(a[0]), "r"(a[1]), "r"(a[2]), "r"(a[3]), "r"(b0), "r"(b1));
}

// ---------------------------------------------------------------------------
// Pre-pass: fp32 -> fp16 conversions
// ---------------------------------------------------------------------------
__global__ void cvt_x_kernel(const float* __restrict__ x) {
    const size_t total4 = (size_t)M_GEMM * K_GEMM / 4;
    size_t stride = (size_t)gridDim.x * blockDim.x;
    for (size_t i = (size_t)blockIdx.x * blockDim.x + threadIdx.x; i < total4; i += stride) {
        float4 v = ((const float4*)x)[i];
        __half2* dst = (__half2*)(g_xh + i * 4);
        dst[0] = __floats2half2_rn(v.x, v.y);
        dst[1] = __floats2half2_rn(v.z, v.w);
    }
}
__global__ void cvt_w_kernel(const float* __restrict__ w) {
    const size_t total4 = (size_t)K_GEMM * N_GEMM / 4;
    size_t stride = (size_t)gridDim.x * blockDim.x;
    for (size_t i = (size_t)blockIdx.x * blockDim.x + threadIdx.x; i < total4; i += stride) {
        float4 v = ((const float4*)w)[i];
        __half2* dst = (__half2*)(g_wh + i * 4);
        dst[0] = __floats2half2_rn(v.x, v.y);
        dst[1] = __floats2half2_rn(v.z, v.w);
    }
}

// ---------------------------------------------------------------------------
// HMMA GEMM: h[M,N] = xh[M,K] * wh[K,N], h stored fp16
// ---------------------------------------------------------------------------
__device__ __forceinline__ void issue_loads(int tid, int chunk, int block_m, int block_n,
                                            uint32_t smem_base) {
    const int k0 = chunk * BK;
    const uint32_t sb = smem_base + (chunk % STAGES) * STAGE_BYTES;
    // A tile: 256 rows x 64B = 1024 x 16B chunks (2/thread @ 512 threads)
#pragma unroll
    for (int i = 0; i < 2; i++) {
        int idx = tid + i * 512;
        int r = idx >> 2, q = idx & 3;
        cp16(sb + r * A_STRIDE + q * 16,
             g_xh + (size_t)(block_m + r) * K_GEMM + k0 + q * 8);
    }
    // B tile: 32 rows x 256B = 512 x 16B chunks (1/thread)
    {
        int r = tid >> 4, q = tid & 15;
        cp16(sb + A_STAGE_BYTES + r * B_STRIDE + q * 16,
             g_wh + (size_t)(k0 + r) * N_GEMM + block_n + q * 8);
    }
    CP_COMMIT();
}

__global__ void __launch_bounds__(512, 1)
gemm_hmma_kernel() {
    extern __shared__ char smem[];
    const uint32_t sbase = smem_u32(smem);
    const int tid  = threadIdx.x;
    const int wid  = tid >> 5;
    const int lane = tid & 31;
    const int wm = wid >> 1;          // 0..7  (32-row slab)
    const int wn = wid & 1;           // 0..1  (64-col slab)
    const int block_m = blockIdx.y * BM;
    const int block_n = blockIdx.x * BN;

    float c[2][8][4] = {};            // 64 accumulators

    // Prologue: stages 0..3
#pragma unroll
    for (int p = 0; p < STAGES - 1; p++) issue_loads(tid, p, block_m, block_n, sbase);

    const int a_row  = wm * 32 + (lane & 15);               // + mf*16
    const int a_colb = ((lane >> 4) & 1) * 16;              // bytes; + ks*32
    const int b_krow = (lane & 7) + ((lane >> 3) & 1) * 8;  // + ks*16
    const int b_ncol = wn * 64 + ((lane >> 4) & 1) * 8;     // + p*16

#pragma unroll 1
    for (int ch = 0; ch < NCHUNK; ch++) {
        asm volatile("cp.async.wait_group 3;" ::: "memory");
        __syncthreads();

        if (ch + STAGES - 1 < NCHUNK)
            issue_loads(tid, ch + STAGES - 1, block_m, block_n, sbase);
        else
            CP_COMMIT();   // keep group-count invariant

        const uint32_t aB = sbase + (ch % STAGES) * STAGE_BYTES;
        const uint32_t bB = aB + A_STAGE_BYTES;

#pragma unroll
        for (int ks = 0; ks < 2; ks++) {
            uint32_t a[2][4], b[4][4];
#pragma unroll
            for (int mf = 0; mf < 2; mf++)
                ldsm_x4(a[mf], aB + (a_row + mf * 16) * A_STRIDE + ks * 32 + a_colb);
#pragma unroll
            for (int p = 0; p < 4; p++)
                ldsm_x4_t(b[p], bB + (b_krow + ks * 16) * B_STRIDE
                                   + (b_ncol + p * 16) * 2);
#pragma unroll
            for (int mf = 0; mf < 2; mf++)
#pragma unroll
                for (int nf = 0; nf < 8; nf++)
                    mma16816(c[mf][nf], a[mf],
                             b[nf >> 1][(nf & 1) * 2], b[nf >> 1][(nf & 1) * 2 + 1]);
        }
    }

    // Epilogue: fp32 acc -> half2 stores to g_h
    const int m0 = block_m + wm * 32 + (lane >> 2);
    const int n0 = block_n + wn * 64 + (lane & 3) * 2;
#pragma unroll
    for (int mf = 0; mf < 2; mf++) {
#pragma unroll
        for (int nf = 0; nf < 8; nf++) {
            __half* p0 = g_h + (size_t)(m0 + mf * 16) * N_GEMM + n0 + nf * 8;
            *(__half2*)p0 = __floats2half2_rn(c[mf][nf][0], c[mf][nf][1]);
            *(__half2*)(p0 + 8 * N_GEMM) = __floats2half2_rn(c[mf][nf][2], c[mf][nf][3]);
        }
    }
}

// ---------------------------------------------------------------------------
// Scan: syn[b,0]=0 ; syn[b,t] = decay*syn[b,t-1] + h[b,t-1]
// One thread per (b, 4 consecutive o). h read as fp16 (uint2 = 4 halves).
// ---------------------------------------------------------------------------
__global__ void __launch_bounds__(256)
scan_kernel(const float* __restrict__ alpha, const float* __restrict__ beta,
            float* __restrict__ out) {
    const int idx = blockIdx.x * blockDim.x + threadIdx.x;  // 0 .. B*O/4-1
    const int b = idx >> 9;             // O/4 = 512 quads per batch
    const int o = (idx & 511) << 2;

    float4 a4 = *(const float4*)(alpha + o);
    float4 b4 = *(const float4*)(beta + o);
    float4 d = make_float4(a4.x * (1.f - b4.x), a4.y * (1.f - b4.y),
                           a4.z * (1.f - b4.z), a4.w * (1.f - b4.w));

    const uint2* hp = (const uint2*)(g_h + (size_t)b * TDIM * ODIM + o);  // 4 halves
    float4*      op = (float4*)(out + (size_t)b * TDIM * ODIM + o);
    const int hs = ODIM / 4;   // uint2 stride per t
    const int os = ODIM / 4;   // float4 stride per t

    float4 syn = make_float4(0.f, 0.f, 0.f, 0.f);
    op[0] = syn;

#pragma unroll 4
    for (int t = 1; t < TDIM; t++) {
        uint2 hv = hp[(size_t)(t - 1) * hs];
        float2 f0 = __half22float2(*(const __half2*)&hv.x);
        float2 f1 = __half22float2(*(const __half2*)&hv.y);
        syn.x = fmaf(d.x, syn.x, f0.x);
        syn.y = fmaf(d.y, syn.y, f0.y);
        syn.z = fmaf(d.z, syn.z, f1.x);
        syn.w = fmaf(d.w, syn.w, f1.y);
        op[(size_t)t * os] = syn;
    }
}

// ---------------------------------------------------------------------------
extern "C" void kernel_launch(void* const* d_in, const int* in_sizes, int n_in,
                              void* d_out, int out_size)
{
    const float* x     = (const float*)d_in[0];
    const float* w     = (const float*)d_in[1];
    const float* alpha = (const float*)d_in[2];
    const float* beta  = (const float*)d_in[3];
    float* out         = (float*)d_out;

    cudaFuncSetAttribute(gemm_hmma_kernel,
                         cudaFuncAttributeMaxDynamicSharedMemorySize, SMEM_TOTAL);

    cvt_x_kernel<<<4096, 256>>>(x);
    cvt_w_kernel<<<512, 256>>>(w);

    dim3 grid(N_GEMM / BN, M_GEMM / BM);   // (16, 500); x-fast => A-panel L2 reuse
    gemm_hmma_kernel<<<grid, 512, SMEM_TOTAL>>>();

    scan_kernel<<<BDIM * (ODIM / 4) / 256, 256>>>(alpha, beta, out);
}

// round 8
// speedup vs baseline: 1.2316x; 1.2316x over previous
#include <cuda_runtime.h>
#include <cuda_fp16.h>
#include <cstdint>

// Problem dims (fixed)
#define BDIM 256
#define TDIM 500
#define IDIM 1024
#define ODIM 2048
#define M_GEMM (BDIM * TDIM)   // 128000
#define N_GEMM ODIM            // 2048
#define K_GEMM IDIM            // 1024

// GEMM tiling: 128x128 CTA (R6 proven), 8 warps 4(m) x 2(n), 32x64/warp, BK=64
#define BM 128
#define BN 128
#define BK 64
#define STAGES 3
#define NCHUNK (K_GEMM / BK)   // 16

// Padded smem strides (bytes): 16B-chunk counts == 1 mod 8 -> conflict-free ldmatrix
#define A_STRIDE 144           // 64 halves (128B) + 16B pad  (9 chunks)
#define B_STRIDE 272           // 128 halves (256B) + 16B pad (17 chunks)
#define A_STAGE_BYTES (128 * A_STRIDE)   // 18432
#define B_STAGE_BYTES (64 * B_STRIDE)    // 17408
#define STAGE_BYTES (A_STAGE_BYTES + B_STAGE_BYTES)  // 35840
#define SMEM_TOTAL (STAGES * STAGE_BYTES)            // 107520 (2 CTA/SM: 210KB)

// Device scratch (no runtime allocation allowed)
__device__ __align__(1024) __half g_h [(size_t)M_GEMM * N_GEMM];  // 512 MB (h in fp16)
__device__ __align__(1024) __half g_xh[(size_t)M_GEMM * K_GEMM];  // 256 MB
__device__ __align__(1024) __half g_wh[(size_t)K_GEMM * N_GEMM];  // 4 MB

// ---------------------------------------------------------------------------
__device__ __forceinline__ uint32_t smem_u32(const void* p) {
    uint32_t a;
    asm("{ .reg .u64 t; cvta.to.shared.u64 t, %1; cvt.u32.u64 %0, t; }" : "=r"(a) : "l"(p));
    return a;
}
__device__ __forceinline__ void cp16(uint32_t dst, const void* src) {
    asm volatile("cp.async.cg.shared.global [%0], [%1], 16;" :: "r"(dst), "l"(src));
}
#define CP_COMMIT() asm volatile("cp.async.commit_group;" ::: "memory")

__device__ __forceinline__ void ldsm_x4(uint32_t* r, uint32_t addr) {
    asm volatile("ldmatrix.sync.aligned.m8n8.x4.shared.b16 {%0,%1,%2,%3}, [%4];"
                 : "=r"(r[0]), "=r"(r[1]), "=r"(r[2]), "=r"(r[3]) : "r"(addr));
}
__device__ __forceinline__ void ldsm_x4_t(uint32_t* r, uint32_t addr) {
    asm volatile("ldmatrix.sync.aligned.m8n8.x4.trans.shared.b16 {%0,%1,%2,%3}, [%4];"
                 : "=r"(r[0]), "=r"(r[1]), "=r"(r[2]), "=r"(r[3]) : "r"(addr));
}
__device__ __forceinline__ void mma16816(float* c, const uint32_t* a, uint32_t b0, uint32_t b1) {
    asm volatile(
        "mma.sync.aligned.m16n8k16.row.col.f32.f16.f16.f32 "
        "{%0,%1,%2,%3}, {%4,%5,%6,%7}, {%8,%9}, {%0,%1,%2,%3};"
        : "+f"(c[0]), "+f"(c[1]), "+f"(c[2]), "+f"(c[3])
        : "r"(a[0]), "r"(a[1]), "r"(a[2]), "r"(a[3]), "r"(b0), "r"(b1));
}

// ---------------------------------------------------------------------------
// Pre-pass: fp32 -> fp16 conversions
// ---------------------------------------------------------------------------
__global__ void cvt_x_kernel(const float* __restrict__ x) {
    const size_t total4 = (size_t)M_GEMM * K_GEMM / 4;
    size_t stride = (size_t)gridDim.x * blockDim.x;
    for (size_t i = (size_t)blockIdx.x * blockDim.x + threadIdx.x; i < total4; i += stride) {
        float4 v = __ldg((const float4*)x + i);
        __half2* dst = (__half2*)(g_xh + i * 4);
        dst[0] = __floats2half2_rn(v.x, v.y);
        dst[1] = __floats2half2_rn(v.z, v.w);
    }
}
__global__ void cvt_w_kernel(const float* __restrict__ w) {
    const size_t total4 = (size_t)K_GEMM * N_GEMM / 4;
    size_t stride = (size_t)gridDim.x * blockDim.x;
    for (size_t i = (size_t)blockIdx.x * blockDim.x + threadIdx.x; i < total4; i += stride) {
        float4 v = __ldg((const float4*)w + i);
        __half2* dst = (__half2*)(g_wh + i * 4);
        dst[0] = __floats2half2_rn(v.x, v.y);
        dst[1] = __floats2half2_rn(v.z, v.w);
    }
}

// ---------------------------------------------------------------------------
// HMMA GEMM: h[M,N] = xh[M,K] * wh[K,N], h stored fp16
// ---------------------------------------------------------------------------
__device__ __forceinline__ void issue_loads(int tid, int chunk, int block_m, int block_n,
                                            uint32_t smem_base) {
    const int k0 = chunk * BK;
    const uint32_t sb = smem_base + (chunk % STAGES) * STAGE_BYTES;
    // A tile: 128 rows x 128B = 1024 x 16B chunks (4/thread)
#pragma unroll
    for (int i = 0; i < 4; i++) {
        int idx = tid + i * 256;
        int r = idx >> 3, q = idx & 7;
        cp16(sb + r * A_STRIDE + q * 16,
             g_xh + (size_t)(block_m + r) * K_GEMM + k0 + q * 8);
    }
    // B tile: 64 rows x 256B = 1024 x 16B chunks (4/thread)
#pragma unroll
    for (int i = 0; i < 4; i++) {
        int idx = tid + i * 256;
        int r = idx >> 4, q = idx & 15;
        cp16(sb + A_STAGE_BYTES + r * B_STRIDE + q * 16,
             g_wh + (size_t)(k0 + r) * N_GEMM + block_n + q * 8);
    }
    CP_COMMIT();
}

__global__ void __launch_bounds__(256, 2)
gemm_hmma_kernel() {
    extern __shared__ char smem[];
    const uint32_t sbase = smem_u32(smem);
    const int tid  = threadIdx.x;
    const int wid  = tid >> 5;
    const int lane = tid & 31;
    const int wm = wid >> 1;          // 0..3  (32-row slab)
    const int wn = wid & 1;           // 0..1  (64-col slab)
    const int block_m = blockIdx.y * BM;
    const int block_n = blockIdx.x * BN;

    float c[2][8][4] = {};            // 64 accumulators

    // Prologue: stages 0..1
#pragma unroll
    for (int p = 0; p < STAGES - 1; p++) issue_loads(tid, p, block_m, block_n, sbase);

    const int a_row  = wm * 32 + (lane & 15);               // + mf*16
    const int a_colb = ((lane >> 4) & 1) * 16;              // bytes; + ks*32
    const int b_krow = (lane & 7) + ((lane >> 3) & 1) * 8;  // + ks*16
    const int b_ncol = wn * 64 + ((lane >> 4) & 1) * 8;     // + p*16

#pragma unroll 1
    for (int ch = 0; ch < NCHUNK; ch++) {
        asm volatile("cp.async.wait_group 1;" ::: "memory");
        __syncthreads();

        if (ch + STAGES - 1 < NCHUNK)
            issue_loads(tid, ch + STAGES - 1, block_m, block_n, sbase);
        else
            CP_COMMIT();   // keep group-count invariant

        const uint32_t aB = sbase + (ch % STAGES) * STAGE_BYTES;
        const uint32_t bB = aB + A_STAGE_BYTES;

#pragma unroll
        for (int ks = 0; ks < 4; ks++) {    // four k16 steps per 64-chunk
            uint32_t a[2][4], b[4][4];
#pragma unroll
            for (int mf = 0; mf < 2; mf++)
                ldsm_x4(a[mf], aB + (a_row + mf * 16) * A_STRIDE + ks * 32 + a_colb);
#pragma unroll
            for (int p = 0; p < 4; p++)
                ldsm_x4_t(b[p], bB + (b_krow + ks * 16) * B_STRIDE
                                   + (b_ncol + p * 16) * 2);
#pragma unroll
            for (int mf = 0; mf < 2; mf++)
#pragma unroll
                for (int nf = 0; nf < 8; nf++)
                    mma16816(c[mf][nf], a[mf],
                             b[nf >> 1][(nf & 1) * 2], b[nf >> 1][(nf & 1) * 2 + 1]);
        }
    }

    // Epilogue: fp32 acc -> half2 stores to g_h
    const int m0 = block_m + wm * 32 + (lane >> 2);
    const int n0 = block_n + wn * 64 + (lane & 3) * 2;
#pragma unroll
    for (int mf = 0; mf < 2; mf++) {
#pragma unroll
        for (int nf = 0; nf < 8; nf++) {
            __half* p0 = g_h + (size_t)(m0 + mf * 16) * N_GEMM + n0 + nf * 8;
            *(__half2*)p0 = __floats2half2_rn(c[mf][nf][0], c[mf][nf][1]);
            *(__half2*)(p0 + 8 * N_GEMM) = __floats2half2_rn(c[mf][nf][2], c[mf][nf][3]);
        }
    }
}

// ---------------------------------------------------------------------------
// Scan: syn[b,0]=0 ; syn[b,t] = decay*syn[b,t-1] + h[b,t-1]
// One thread per (b, 4 consecutive o). h read via __ldg (breaks false aliasing
// with the out stores -> unrolled loads batch -> MLP 4).
// ---------------------------------------------------------------------------
__global__ void __launch_bounds__(256)
scan_kernel(const float* __restrict__ alpha, const float* __restrict__ beta,
            float* __restrict__ out) {
    const int idx = blockIdx.x * blockDim.x + threadIdx.x;  // 0 .. B*O/4-1
    const int b = idx >> 9;             // O/4 = 512 quads per batch
    const int o = (idx & 511) << 2;

    float4 a4 = *(const float4*)(alpha + o);
    float4 b4 = *(const float4*)(beta + o);
    float4 d = make_float4(a4.x * (1.f - b4.x), a4.y * (1.f - b4.y),
                           a4.z * (1.f - b4.z), a4.w * (1.f - b4.w));

    const uint2* hp = (const uint2*)(g_h + (size_t)b * TDIM * ODIM + o);  // 4 halves
    float4*      op = (float4*)(out + (size_t)b * TDIM * ODIM + o);
    const int hs = ODIM / 4;   // uint2 stride per t
    const int os = ODIM / 4;   // float4 stride per t

    float4 syn = make_float4(0.f, 0.f, 0.f, 0.f);
    op[0] = syn;

#pragma unroll 4
    for (int t = 1; t < TDIM; t++) {
        uint2 hv = __ldg(hp + (size_t)(t - 1) * hs);
        float2 f0 = __half22float2(*(const __half2*)&hv.x);
        float2 f1 = __half22float2(*(const __half2*)&hv.y);
        syn.x = fmaf(d.x, syn.x, f0.x);
        syn.y = fmaf(d.y, syn.y, f0.y);
        syn.z = fmaf(d.z, syn.z, f1.x);
        syn.w = fmaf(d.w, syn.w, f1.y);
        op[(size_t)t * os] = syn;
    }
}

// ---------------------------------------------------------------------------
extern "C" void kernel_launch(void* const* d_in, const int* in_sizes, int n_in,
                              void* d_out, int out_size)
{
    const float* x     = (const float*)d_in[0];
    const float* w     = (const float*)d_in[1];
    const float* alpha = (const float*)d_in[2];
    const float* beta  = (const float*)d_in[3];
    float* out         = (float*)d_out;

    cudaFuncSetAttribute(gemm_hmma_kernel,
                         cudaFuncAttributeMaxDynamicSharedMemorySize, SMEM_TOTAL);

    cvt_x_kernel<<<4096, 256>>>(x);
    cvt_w_kernel<<<512, 256>>>(w);

    dim3 grid(N_GEMM / BN, M_GEMM / BM);   // (16, 1000); x-fast => A-panel L2 reuse
    gemm_hmma_kernel<<<grid, 256, SMEM_TOTAL>>>();

    scan_kernel<<<BDIM * (ODIM / 4) / 256, 256>>>(alpha, beta, out);
}

// round 11
// speedup vs baseline: 1.3119x; 1.0651x over previous
#include <cuda_runtime.h>
#include <cuda_fp16.h>
#include <cstdint>

// Problem dims (fixed)
#define BDIM 256
#define TDIM 500
#define IDIM 1024
#define ODIM 2048
#define M_GEMM (BDIM * TDIM)   // 128000
#define N_GEMM ODIM            // 2048
#define K_GEMM IDIM            // 1024

// GEMM tiling (R8 proven mainloop): 128x128 tile, 8 warps 4(m) x 2(n), BK=64
#define BM 128
#define BN 128
#define BK 64
#define STAGES 3
#define NCHUNK (K_GEMM / BK)   // 16
#define MTILES 4               // 4 x 128 T-rows per CTA (500 clamped to 512)

// Padded smem strides (bytes): 16B-chunk counts == 1 mod 8 -> conflict-free ldmatrix
#define A_STRIDE 144           // 64 halves (128B) + 16B pad  (9 chunks)
#define B_STRIDE 272           // 128 halves (256B) + 16B pad (17 chunks)
#define A_STAGE_BYTES (128 * A_STRIDE)   // 18432
#define B_STAGE_BYTES (64 * B_STRIDE)    // 17408
#define STAGE_BYTES (A_STAGE_BYTES + B_STAGE_BYTES)  // 35840
#define SMEM_TOTAL (STAGES * STAGE_BYTES)            // 107520 (2 CTA/SM)

// Scan buffer: fp32 h-tile 128 rows x 128 cols, pitch 132 floats (67584 B).
// Lives in stages 1..2 (offset STAGE_BYTES, 67584 <= 71680). Stage 0 stays
// free for prefetching the next tile's chunk 0 during the scan.
#define BUF_OFF  STAGE_BYTES
#define BUF_PITCH 132

// Device scratch (no runtime allocation allowed)
__device__ __align__(1024) __half g_xh[(size_t)M_GEMM * K_GEMM];  // 256 MB
__device__ __align__(1024) __half g_wh[(size_t)K_GEMM * N_GEMM];  // 4 MB

// ---------------------------------------------------------------------------
__device__ __forceinline__ uint32_t smem_u32(const void* p) {
    uint32_t a;
    asm("{ .reg .u64 t; cvta.to.shared.u64 t, %1; cvt.u32.u64 %0, t; }" : "=r"(a) : "l"(p));
    return a;
}
__device__ __forceinline__ void cp16(uint32_t dst, const void* src) {
    asm volatile("cp.async.cg.shared.global [%0], [%1], 16;" :: "r"(dst), "l"(src));
}
#define CP_COMMIT() asm volatile("cp.async.commit_group;" ::: "memory")

__device__ __forceinline__ void ldsm_x4(uint32_t* r, uint32_t addr) {
    asm volatile("ldmatrix.sync.aligned.m8n8.x4.shared.b16 {%0,%1,%2,%3}, [%4];"
                 : "=r"(r[0]), "=r"(r[1]), "=r"(r[2]), "=r"(r[3]) : "r"(addr));
}
__device__ __forceinline__ void ldsm_x4_t(uint32_t* r, uint32_t addr) {
    asm volatile("ldmatrix.sync.aligned.m8n8.x4.trans.shared.b16 {%0,%1,%2,%3}, [%4];"
                 : "=r"(r[0]), "=r"(r[1]), "=r"(r[2]), "=r"(r[3]) : "r"(addr));
}
__device__ __forceinline__ void mma16816(float* c, const uint32_t* a, uint32_t b0, uint32_t b1) {
    asm volatile(
        "mma.sync.aligned.m16n8k16.row.col.f32.f16.f16.f32 "
        "{%0,%1,%2,%3}, {%4,%5,%6,%7}, {%8,%9}, {%0,%1,%2,%3};"
        : "+f"(c[0]), "+f"(c[1]), "+f"(c[2]), "+f"(c[3])
        : "r"(a[0]), "r"(a[1]), "r"(a[2]), "r"(a[3]), "r"(b0), "r"(b1));
}

// ---------------------------------------------------------------------------
// Pre-pass: fp32 -> fp16 conversions
// ---------------------------------------------------------------------------
__global__ void cvt_x_kernel(const float* __restrict__ x) {
    const size_t total4 = (size_t)M_GEMM * K_GEMM / 4;
    size_t stride = (size_t)gridDim.x * blockDim.x;
    for (size_t i = (size_t)blockIdx.x * blockDim.x + threadIdx.x; i < total4; i += stride) {
        float4 v = __ldg((const float4*)x + i);
        __half2* dst = (__half2*)(g_xh + i * 4);
        dst[0] = __floats2half2_rn(v.x, v.y);
        dst[1] = __floats2half2_rn(v.z, v.w);
    }
}
__global__ void cvt_w_kernel(const float* __restrict__ w) {
    const size_t total4 = (size_t)K_GEMM * N_GEMM / 4;
    size_t stride = (size_t)gridDim.x * blockDim.x;
    for (size_t i = (size_t)blockIdx.x * blockDim.x + threadIdx.x; i < total4; i += stride) {
        float4 v = __ldg((const float4*)w + i);
        __half2* dst = (__half2*)(g_wh + i * 4);
        dst[0] = __floats2half2_rn(v.x, v.y);
        dst[1] = __floats2half2_rn(v.z, v.w);
    }
}

// ---------------------------------------------------------------------------
// Fused GEMM + scan. CTA = (batch b, 128-col N-block). 4 M-tiles of 128 T-rows.
// ---------------------------------------------------------------------------
__device__ __forceinline__ void issue_loads(int tid, int t0, int chunk,
                                            const __half* aSrc, int block_n,
                                            uint32_t smem_base) {
    const int k0 = chunk * BK;
    const uint32_t sb = smem_base + (chunk % STAGES) * STAGE_BYTES;
#pragma unroll
    for (int i = 0; i < 4; i++) {   // A: 128 rows x 128B; T-row clamped to 499
        int idx = tid + i * 256;
        int r = idx >> 3, q = idx & 7;
        int t = t0 + r; if (t > TDIM - 1) t = TDIM - 1;
        cp16(sb + r * A_STRIDE + q * 16,
             aSrc + (size_t)t * K_GEMM + k0 + q * 8);
    }
#pragma unroll
    for (int i = 0; i < 4; i++) {   // B: 64 rows x 256B
        int idx = tid + i * 256;
        int r = idx >> 4, q = idx & 15;
        cp16(sb + A_STAGE_BYTES + r * B_STRIDE + q * 16,
             g_wh + (size_t)(k0 + r) * N_GEMM + block_n + q * 8);
    }
    CP_COMMIT();
}

__global__ void __launch_bounds__(256, 2)
fused_gemm_scan_kernel(const float* __restrict__ alpha,
                       const float* __restrict__ beta,
                       float* __restrict__ out) {
    extern __shared__ char smem[];
    const uint32_t sbase = smem_u32(smem);
    float* buf = (float*)(smem + BUF_OFF);

    const int tid  = threadIdx.x;
    const int wid  = tid >> 5;
    const int lane = tid & 31;
    const int wm = wid >> 1;          // 0..3
    const int wn = wid & 1;           // 0..1
    const int b       = blockIdx.y;
    const int block_n = blockIdx.x * BN;
    const __half* aSrc = g_xh + (size_t)b * TDIM * K_GEMM;
    float* outB = out + (size_t)b * TDIM * ODIM + block_n;

    // scan state (threads 0..127 own one output column each)
    float syn = 0.0f, decay = 0.0f;
    if (tid < BN) decay = alpha[block_n + tid] * (1.0f - beta[block_n + tid]);

    const int a_row  = wm * 32 + (lane & 15);
    const int a_colb = ((lane >> 4) & 1) * 16;
    const int b_krow = (lane & 7) + ((lane >> 3) & 1) * 8;
    const int b_ncol = wn * 64 + ((lane >> 4) & 1) * 8;
    const int m0l = wm * 32 + (lane >> 2);
    const int n0l = wn * 64 + (lane & 3) * 2;

    // Pre-issue tile 0 chunk 0 (stage 0)
    issue_loads(tid, 0, 0, aSrc, block_n, sbase);

#pragma unroll 1
    for (int tile = 0; tile < MTILES; tile++) {
        const int t0 = tile * BM;
        float c[2][8][4] = {};

        // chunk 1 prologue (chunk 0 was prefetched before the previous scan)
        issue_loads(tid, t0, 1, aSrc, block_n, sbase);

#pragma unroll 1
        for (int ch = 0; ch < NCHUNK; ch++) {
            asm volatile("cp.async.wait_group 1;" ::: "memory");
            __syncthreads();

            if (ch + STAGES - 1 < NCHUNK)
                issue_loads(tid, t0, ch + STAGES - 1, aSrc, block_n, sbase);
            else
                CP_COMMIT();   // keep group-count invariant

            const uint32_t aB = sbase + (ch % STAGES) * STAGE_BYTES;
            const uint32_t bB = aB + A_STAGE_BYTES;

#pragma unroll
            for (int ks = 0; ks < 4; ks++) {
                uint32_t a[2][4], bb[4][4];
#pragma unroll
                for (int mf = 0; mf < 2; mf++)
                    ldsm_x4(a[mf], aB + (a_row + mf * 16) * A_STRIDE + ks * 32 + a_colb);
#pragma unroll
                for (int p = 0; p < 4; p++)
                    ldsm_x4_t(bb[p], bB + (b_krow + ks * 16) * B_STRIDE
                                       + (b_ncol + p * 16) * 2);
#pragma unroll
                for (int mf = 0; mf < 2; mf++)
#pragma unroll
                    for (int nf = 0; nf < 8; nf++)
                        mma16816(c[mf][nf], a[mf],
                                 bb[nf >> 1][(nf & 1) * 2], bb[nf >> 1][(nf & 1) * 2 + 1]);
            }
        }

        // BARRIER FIRST: all warps' ldmatrix reads of every stage (incl. stage 0
        // used by ch=15) must retire before anyone overwrites stage 0 (prefetch)
        // or stages 1..2 (scan buffer). This was the R10 WAR race.
        __syncthreads();

        // Prefetch next tile's chunk 0 into stage 0 (disjoint from scan buffer)
        if (tile + 1 < MTILES)
            issue_loads(tid, t0 + BM, 0, aSrc, block_n, sbase);
        else
            CP_COMMIT();

        // Accumulators -> fp32 smem buffer (pitch 132 floats)
#pragma unroll
        for (int mf = 0; mf < 2; mf++) {
#pragma unroll
            for (int nf = 0; nf < 8; nf++) {
                int r0 = m0l + mf * 16;
                int cc = n0l + nf * 8;
                *(float2*)(buf + r0 * BUF_PITCH + cc) =
                    make_float2(c[mf][nf][0], c[mf][nf][1]);
                *(float2*)(buf + (r0 + 8) * BUF_PITCH + cc) =
                    make_float2(c[mf][nf][2], c[mf][nf][3]);
            }
        }
        __syncthreads();

        // Sequential scan over this tile's 128 T-steps (threads 0..127)
        if (tid < BN) {
            if (tile == 0) outB[tid] = 0.0f;   // out[b, 0, :] = 0
#pragma unroll 4
            for (int i = 0; i < BM; i++) {
                int t_out = t0 + i + 1;
                if (t_out < TDIM) {
                    syn = fmaf(decay, syn, buf[i * BUF_PITCH + tid]);
                    outB[(size_t)t_out * ODIM + tid] = syn;
                }
            }
        }
        __syncthreads();   // scan done -> next tile may overwrite buf stages
    }
}

// ---------------------------------------------------------------------------
extern "C" void kernel_launch(void* const* d_in, const int* in_sizes, int n_in,
                              void* d_out, int out_size)
{
    const float* x     = (const float*)d_in[0];
    const float* w     = (const float*)d_in[1];
    const float* alpha = (const float*)d_in[2];
    const float* beta  = (const float*)d_in[3];
    float* out         = (float*)d_out;

    cudaFuncSetAttribute(fused_gemm_scan_kernel,
                         cudaFuncAttributeMaxDynamicSharedMemorySize, SMEM_TOTAL);

    cvt_x_kernel<<<4096, 256>>>(x);
    cvt_w_kernel<<<512, 256>>>(w);

    dim3 grid(N_GEMM / BN, BDIM);   // (16, 256); x-fast => A-panel L2 reuse
    fused_gemm_scan_kernel<<<grid, 256, SMEM_TOTAL>>>(alpha, beta, out);
}